// round 17
// baseline (speedup 1.0000x reference)
#include <cuda_runtime.h>
#include <cuda_fp16.h>
#include <cstdint>

#define BSZ 2
#define LQ 2048
#define DM 256
#define MROWS (BSZ*LQ)
#define SPLITS 2

// scratch
__device__ __half g_Qh[MROWS*DM];
__device__ __half g_Kh[MROWS*DM];
__device__ __half g_Vh[MROWS*DM];
__device__ __half g_msgh[MROWS*DM];
__device__ __half g_hidh[MROWS*2*DM];
__device__ __half g_Wqh[DM*DM];
__device__ __half g_Wkh[DM*DM];
__device__ __half g_Wvh[DM*DM];
__device__ __half g_Wmgh[DM*DM];
__device__ __half g_Wm1h[2*DM*2*DM];
__device__ __half g_Wm2h[2*DM*DM];
__device__ __half g_parth[SPLITS*MROWS*DM];
__device__ float g_pstat[SPLITS*MROWS*4*2];

// ---------------------------------------------------------------------------
__device__ __forceinline__ unsigned h2pk(float lo, float hi){
    unsigned r; asm("cvt.rn.f16x2.f32 %0, %1, %2;" : "=r"(r) : "f"(hi), "f"(lo)); return r;
}
__device__ __forceinline__ void ldsm4(unsigned* r, unsigned a){
    asm volatile("ldmatrix.sync.aligned.m8n8.x4.shared.b16 {%0,%1,%2,%3},[%4];"
        : "=r"(r[0]),"=r"(r[1]),"=r"(r[2]),"=r"(r[3]) : "r"(a));
}
__device__ __forceinline__ void ldsm4t(unsigned* r, unsigned a){
    asm volatile("ldmatrix.sync.aligned.m8n8.x4.trans.shared.b16 {%0,%1,%2,%3},[%4];"
        : "=r"(r[0]),"=r"(r[1]),"=r"(r[2]),"=r"(r[3]) : "r"(a));
}
__device__ __forceinline__ void mma16(float* c, const unsigned* a, const unsigned* b){
    asm volatile("mma.sync.aligned.m16n8k16.row.col.f32.f16.f16.f32 "
        "{%0,%1,%2,%3},{%4,%5,%6,%7},{%8,%9},{%0,%1,%2,%3};"
        : "+f"(c[0]), "+f"(c[1]), "+f"(c[2]), "+f"(c[3])
        : "r"(a[0]), "r"(a[1]), "r"(a[2]), "r"(a[3]), "r"(b[0]), "r"(b[1]));
}
__device__ __forceinline__ void cpa16(unsigned dst, const void* src){
    asm volatile("cp.async.cg.shared.global [%0], [%1], 16;" :: "r"(dst), "l"(src));
}
__device__ __forceinline__ void cpa4(unsigned dst, const void* src){
    asm volatile("cp.async.ca.shared.global [%0], [%1], 4;" :: "r"(dst), "l"(src));
}
#define CPA_COMMIT() asm volatile("cp.async.commit_group;" ::: "memory")
#define CPA_WAIT0()  asm volatile("cp.async.wait_group 0;" ::: "memory")

// e^x for x <= 0, FMA-pipe only. rel err ~2e-6.
__device__ __forceinline__ float fast_exp(float x){
    float y = x * 1.44269504f;
    y = fmaxf(y, -126.0f);
    float z = y + 12582912.0f;
    int   n = __float_as_int(z) - 0x4B400000;
    float f = y - (z - 12582912.0f);
    float p = 1.33336e-3f;
    p = fmaf(p, f, 9.61813e-3f);
    p = fmaf(p, f, 5.55041e-2f);
    p = fmaf(p, f, 2.40227e-1f);
    p = fmaf(p, f, 6.93147e-1f);
    p = fmaf(p, f, 1.0f);
    return p * __int_as_float((n + 127) << 23);
}

// ---------------------------------------------------------------------------
// prep: convert WEIGHTS ONLY to fp16. Wq pre-scaled by 1/8 (exact).
// ---------------------------------------------------------------------------
#define W_S0 16384L
#define W_S1 32768L
#define W_S2 49152L
#define W_S3 65536L
#define W_S4 131072L
#define W_S5 163840L
#define PREP_GRID ((W_S5 + 255) / 256)

__global__ void __launch_bounds__(256) k_prep(
    const float* Wq, const float* Wk, const float* Wv, const float* Wmg,
    const float* Wm1, const float* Wm2)
{
    long i = (long)blockIdx.x*256 + threadIdx.x;
    if (i >= W_S5) return;
    float4 v; __half* dst;
    if (i < W_S0){
        v = ((const float4*)Wq)[i];
        v.x *= 0.125f; v.y *= 0.125f; v.z *= 0.125f; v.w *= 0.125f;
        dst = g_Wqh + i*4;
    } else if (i < W_S1){
        long j = i - W_S0; v = ((const float4*)Wk)[j]; dst = g_Wkh + j*4;
    } else if (i < W_S2){
        long j = i - W_S1; v = ((const float4*)Wv)[j]; dst = g_Wvh + j*4;
    } else if (i < W_S3){
        long j = i - W_S2; v = ((const float4*)Wmg)[j]; dst = g_Wmgh + j*4;
    } else if (i < W_S4){
        long j = i - W_S3; v = ((const float4*)Wm1)[j]; dst = g_Wm1h + j*4;
    } else {
        long j = i - W_S4; v = ((const float4*)Wm2)[j]; dst = g_Wm2h + j*4;
    }
    *(uint2*)dst = make_uint2(h2pk(v.x, v.y), h2pk(v.z, v.w));
}

// ---------------------------------------------------------------------------
// fp16 GEMM: BM=32, BN=256, BK=32, 256 threads; B via cp.async double-buffer.
// ---------------------------------------------------------------------------
#define AM_F32    0
#define AM_F32ADD 1
#define AM_CATFH  2
#define AM_H16    3
#define EPI_RELU  1
#define EPI_LNR   3
#define EPI_H16   4

#define AS_H 40
#define BS_H 264
#define BUF_H (32*AS_H + 32*BS_H)
#define SM_GEMM (2*BUF_H*2)

template<int KD, int AM, int EPI>
__device__ __forceinline__ void gemm_h(
    const float* __restrict__ Af, const float* __restrict__ Af2,
    const __half* __restrict__ Ah,
    const __half* __restrict__ Bw, int ldb, int n0,
    const float* __restrict__ gamma, const float* __restrict__ beta,
    const float* __restrict__ resid, void* __restrict__ Cv, int ldc)
{
    extern __shared__ unsigned char smraw[];
    const int KC = KD/32;
    int tid = threadIdx.x;
    int w = tid >> 5, lane = tid & 31;
    int wm = w >> 2, wn = w & 3;
    int g4 = lane >> 2, tig = lane & 3;
    int lrow = (lane & 7) + ((lane >> 3) & 1)*8;
    int lcol8 = (lane >> 4)*8;
    int row0 = blockIdx.x * 32;
    unsigned sb = (unsigned)__cvta_generic_to_shared(smraw);

    float acc[8][4];
    #pragma unroll
    for (int nt = 0; nt < 8; nt++)
        #pragma unroll
        for (int i = 0; i < 4; i++) acc[nt][i] = 0.f;

    auto issueB = [&](int kc){
        unsigned ab = sb + ((kc & 1)*BUF_H)*2;
        unsigned bb = ab + 32*AS_H*2;
        if (AM == AM_H16 && tid < 128){
            int r = tid >> 2, c8 = (tid & 3) << 3;
            cpa16(ab + (r*AS_H + c8)*2, Ah + (row0+r)*KD + kc*32 + c8);
        }
        #pragma unroll
        for (int i = 0; i < 4; i++){
            int id = tid + i*256;
            int r = id >> 5, c8 = (id & 31) << 3;
            cpa16(bb + (r*BS_H + c8)*2, Bw + (kc*32 + r)*ldb + n0 + c8);
        }
    };

    float4 pa; uint2 pah; bool alow = true;
    auto ldgA = [&](int kc){
        if (AM == AM_H16) return;
        int r = tid >> 3, c4 = (tid & 7) << 2;
        int col = kc*32 + c4;
        if (AM == AM_F32){
            pa = *(const float4*)(Af + (row0+r)*KD + col);
        } else if (AM == AM_F32ADD){
            float4 a = *(const float4*)(Af  + (row0+r)*KD + col);
            float4 b = *(const float4*)(Af2 + (row0+r)*KD + col);
            pa = make_float4(a.x+b.x, a.y+b.y, a.z+b.z, a.w+b.w);
        } else {
            alow = col < 256;
            if (alow) pa = *(const float4*)(Af + (row0+r)*256 + col);
            else      pah = *(const uint2*)(Ah + (row0+r)*256 + (col - 256));
        }
    };
    auto stsA = [&](int kc){
        if (AM == AM_H16) return;
        __half* Ab = (__half*)smraw + (kc & 1)*BUF_H;
        int r = tid >> 3, c4 = (tid & 7) << 2;
        uint2 u;
        if (AM == AM_CATFH && !alow) u = pah;
        else u = make_uint2(h2pk(pa.x, pa.y), h2pk(pa.z, pa.w));
        *(uint2*)&Ab[r*AS_H + c4] = u;
    };

    ldgA(0);
    issueB(0); CPA_COMMIT();
    stsA(0);
    CPA_WAIT0(); __syncthreads();

    for (int kc = 0; kc < KC; kc++){
        if (kc + 1 < KC){ issueB(kc+1); CPA_COMMIT(); ldgA(kc+1); }
        unsigned ab = sb + ((kc & 1)*BUF_H)*2;
        unsigned bb = ab + 32*AS_H*2;
        #pragma unroll
        for (int kk = 0; kk < 2; kk++){
            int k0 = kk*16;
            unsigned a[4];
            ldsm4(a, ab + ((wm*16 + lrow)*AS_H + k0 + lcol8)*2);
            #pragma unroll
            for (int j = 0; j < 4; j++){
                unsigned bv[4];
                ldsm4t(bv, bb + ((k0 + lrow)*BS_H + wn*64 + j*16 + lcol8)*2);
                unsigned b0[2] = {bv[0], bv[1]};
                unsigned b1[2] = {bv[2], bv[3]};
                mma16(acc[2*j],   a, b0);
                mma16(acc[2*j+1], a, b1);
            }
        }
        if (kc + 1 < KC){ stsA(kc+1); CPA_WAIT0(); __syncthreads(); }
    }

    if (EPI == EPI_H16 || EPI == EPI_RELU){
        __half* C = (__half*)Cv;
        int rl = row0 + wm*16 + g4;
        #pragma unroll
        for (int nt = 0; nt < 8; nt++){
            int col = n0 + wn*64 + nt*8 + 2*tig;
            float v0 = acc[nt][0], v1 = acc[nt][1];
            float v2 = acc[nt][2], v3 = acc[nt][3];
            if (EPI == EPI_RELU){
                v0=fmaxf(v0,0.f); v1=fmaxf(v1,0.f); v2=fmaxf(v2,0.f); v3=fmaxf(v3,0.f);
            }
            *(unsigned*)(C + rl*ldc + col)     = h2pk(v0, v1);
            *(unsigned*)(C + (rl+8)*ldc + col) = h2pk(v2, v3);
        }
    } else {   // EPI_LNR
        float* C = (float*)Cv;
        __syncthreads();
        float2* red = (float2*)smraw;
        float s1[2] = {0,0}, s2[2] = {0,0};
        #pragma unroll
        for (int nt = 0; nt < 8; nt++){
            float c0=acc[nt][0], c1=acc[nt][1], c2=acc[nt][2], c3=acc[nt][3];
            s1[0] += c0+c1; s2[0] += c0*c0 + c1*c1;
            s1[1] += c2+c3; s2[1] += c2*c2 + c3*c3;
        }
        #pragma unroll
        for (int hb = 0; hb < 2; hb++){
            float v1 = s1[hb], v2 = s2[hb];
            v1 += __shfl_xor_sync(~0u, v1, 1); v1 += __shfl_xor_sync(~0u, v1, 2);
            v2 += __shfl_xor_sync(~0u, v2, 1); v2 += __shfl_xor_sync(~0u, v2, 2);
            if (tig == 0){
                int r = wm*16 + g4 + hb*8;
                red[r*4 + wn] = make_float2(v1, v2);
            }
        }
        __syncthreads();
        #pragma unroll
        for (int hb = 0; hb < 2; hb++){
            int r = wm*16 + g4 + hb*8;
            float S1 = 0.f, S2 = 0.f;
            #pragma unroll
            for (int j = 0; j < 4; j++){ float2 e = red[r*4+j]; S1 += e.x; S2 += e.y; }
            float mean = S1 * (1.f/256.f);
            float var  = S2 * (1.f/256.f) - mean*mean;
            float inv  = rsqrtf(var + 1e-5f);
            int grow = row0 + r;
            #pragma unroll
            for (int nt = 0; nt < 8; nt++){
                int col = wn*64 + nt*8 + 2*tig;
                float c0 = acc[nt][hb*2], c1 = acc[nt][hb*2+1];
                float o0 = (c0 - mean)*inv*gamma[col]   + beta[col] + resid[grow*256 + col];
                float o1 = (c1 - mean)*inv*gamma[col+1] + beta[col+1] + resid[grow*256 + col + 1];
                *(float2*)(C + grow*ldc + col) = make_float2(o0, o1);
            }
        }
    }
}

__global__ void __launch_bounds__(256) k_qkv(
    const float* x, const float* xpe, const float* src, const float* spe)
{
    if (blockIdx.z == 0)      gemm_h<256, AM_F32ADD, EPI_H16>(x,   xpe, 0, g_Wqh, 256, 0, 0,0,0, g_Qh, 256);
    else if (blockIdx.z == 1) gemm_h<256, AM_F32ADD, EPI_H16>(src, spe, 0, g_Wkh, 256, 0, 0,0,0, g_Kh, 256);
    else                      gemm_h<256, AM_F32,    EPI_H16>(src, 0,   0, g_Wvh, 256, 0, 0,0,0, g_Vh, 256);
}
__global__ void __launch_bounds__(256) k_mlp1(const float* x){
    gemm_h<512, AM_CATFH, EPI_RELU>(x, 0, g_msgh, g_Wm1h, 512, blockIdx.y*256, 0,0,0, g_hidh, 512);
}
__global__ void __launch_bounds__(256) k_mlp2(const float* gg, const float* bb,
                                              const float* x, float* out){
    gemm_h<512, AM_H16, EPI_LNR>(0, 0, g_hidh, g_Wm2h, 256, 0, gg, bb, x, out, 256);
}

// ---------------------------------------------------------------------------
// k_merge v2: BM=16 (grid 256 -> full chip + 2 CTAs/SM), fused split-KV
// merge in prologue, B double-buffered via cp.async, LN -> fp16 g_msgh.
// 8 warps = 8 N-slices of 32; warp tile 16x32.
// ---------------------------------------------------------------------------
#define MM_STR 264
#define MM_A   (16*MM_STR)                  // 4224 halves
#define SM_MERGE ((MM_A + 2*32*BS_H)*2)     // 42240 bytes

__global__ void __launch_bounds__(256) k_merge(const float* __restrict__ gamma,
                                               const float* __restrict__ beta)
{
    extern __shared__ unsigned char smraw[];
    __half* Areg = (__half*)smraw;
    int tid = threadIdx.x;
    int wn = tid >> 5, lane = tid & 31;
    int g4 = lane >> 2, tig = lane & 3;
    int lrow = (lane & 7) + ((lane >> 3) & 1)*8;
    int lcol8 = (lane >> 4)*8;
    int row0 = blockIdx.x * 16;
    unsigned sb = (unsigned)__cvta_generic_to_shared(smraw);

    auto issueB = [&](int kc){
        unsigned bb = sb + (MM_A + (kc & 1)*32*BS_H)*2;
        #pragma unroll
        for (int i = 0; i < 4; i++){
            int id = tid + i*256;
            int r = id >> 5, c8 = (id & 31) << 3;
            cpa16(bb + (r*BS_H + c8)*2, g_Wmgh + (kc*32 + r)*256 + c8);
        }
    };

    issueB(0); CPA_COMMIT();

    // merge split partials (16 rows x 256 cols; thread = 16 cols of one row)
    {
        int r = tid >> 4, c0 = (tid & 15) * 16;
        long gr = row0 + r;
        int hh = c0 >> 6;
        float2 ms0 = *(const float2*)&g_pstat[((0L*MROWS + gr)*4 + hh)*2];
        float2 ms1 = *(const float2*)&g_pstat[((1L*MROWS + gr)*4 + hh)*2];
        float M = fmaxf(ms0.x, ms1.x);
        float w0 = fast_exp(ms0.x - M), w1 = fast_exp(ms1.x - M);
        float inv = 1.0f/(ms0.y*w0 + ms1.y*w1);
        w0 *= inv; w1 *= inv;
        #pragma unroll
        for (int i = 0; i < 2; i++){
            uint4 q0 = *(const uint4*)(g_parth + (0L*MROWS + gr)*256 + c0 + i*8);
            uint4 q1 = *(const uint4*)(g_parth + (1L*MROWS + gr)*256 + c0 + i*8);
            const __half2* p0 = (const __half2*)&q0;
            const __half2* p1 = (const __half2*)&q1;
            uint4 o; unsigned* ou = (unsigned*)&o;
            #pragma unroll
            for (int j = 0; j < 4; j++){
                float2 a = __half22float2(p0[j]);
                float2 b = __half22float2(p1[j]);
                ou[j] = h2pk(a.x*w0 + b.x*w1, a.y*w0 + b.y*w1);
            }
            *(uint4*)&Areg[r*MM_STR + c0 + i*8] = o;
        }
    }
    CPA_WAIT0(); __syncthreads();

    float acc[4][4];
    #pragma unroll
    for (int nt = 0; nt < 4; nt++)
        #pragma unroll
        for (int i = 0; i < 4; i++) acc[nt][i] = 0.f;

    for (int kc = 0; kc < 8; kc++){
        if (kc + 1 < 8){ issueB(kc+1); CPA_COMMIT(); }
        unsigned bb = sb + (MM_A + (kc & 1)*32*BS_H)*2;
        #pragma unroll
        for (int kk = 0; kk < 2; kk++){
            int k0 = kc*32 + kk*16;
            unsigned a[4];
            ldsm4(a, sb + (lrow*MM_STR + k0 + lcol8)*2);
            #pragma unroll
            for (int j = 0; j < 2; j++){
                unsigned bv[4];
                ldsm4t(bv, bb + ((kk*16 + lrow)*BS_H + wn*32 + j*16 + lcol8)*2);
                unsigned b0[2] = {bv[0], bv[1]};
                unsigned b1[2] = {bv[2], bv[3]};
                mma16(acc[2*j],   a, b0);
                mma16(acc[2*j+1], a, b1);
            }
        }
        if (kc + 1 < 8){ CPA_WAIT0(); __syncthreads(); }
    }

    // LN epilogue (16 rows, 8 warps per row) -> fp16 g_msgh
    __syncthreads();
    float2* red = (float2*)smraw;   // red[16][8]
    float s1[2] = {0,0}, s2[2] = {0,0};
    #pragma unroll
    for (int nt = 0; nt < 4; nt++){
        float c0=acc[nt][0], c1=acc[nt][1], c2=acc[nt][2], c3=acc[nt][3];
        s1[0] += c0+c1; s2[0] += c0*c0 + c1*c1;
        s1[1] += c2+c3; s2[1] += c2*c2 + c3*c3;
    }
    #pragma unroll
    for (int hb = 0; hb < 2; hb++){
        float v1 = s1[hb], v2 = s2[hb];
        v1 += __shfl_xor_sync(~0u, v1, 1); v1 += __shfl_xor_sync(~0u, v1, 2);
        v2 += __shfl_xor_sync(~0u, v2, 1); v2 += __shfl_xor_sync(~0u, v2, 2);
        if (tig == 0)
            red[(g4 + hb*8)*8 + wn] = make_float2(v1, v2);
    }
    __syncthreads();
    #pragma unroll
    for (int hb = 0; hb < 2; hb++){
        int r = g4 + hb*8;
        float S1 = 0.f, S2 = 0.f;
        #pragma unroll
        for (int j = 0; j < 8; j++){ float2 e = red[r*8+j]; S1 += e.x; S2 += e.y; }
        float mean = S1 * (1.f/256.f);
        float var  = S2 * (1.f/256.f) - mean*mean;
        float inv  = rsqrtf(var + 1e-5f);
        int grow = row0 + r;
        #pragma unroll
        for (int nt = 0; nt < 4; nt++){
            int col = wn*32 + nt*8 + 2*tig;
            float c0 = acc[nt][hb*2], c1 = acc[nt][hb*2+1];
            float o0 = (c0 - mean)*inv*gamma[col]   + beta[col];
            float o1 = (c1 - mean)*inv*gamma[col+1] + beta[col+1];
            *(unsigned*)(g_msgh + grow*256 + col) = h2pk(o0, o1);
        }
    }
}

// ---------------------------------------------------------------------------
// Flash attention v10.1: R16 + float2/int2 comp & mask loads in softmax.
// ---------------------------------------------------------------------------
#define QH 264
#define CS_STR 36
#define AT_K   16896
#define AT_V   33792
#define AT_CB  101376
#define AT_SMS 119808
#define AT_XM  120064
#define ATTN_BYTES 120320

__device__ __forceinline__ void attn_issue_tile(
    const __half* __restrict__ Km, const __half* __restrict__ Vm,
    const float* __restrict__ comp, const int* __restrict__ smask,
    unsigned sb, int buf, int b, int l0, int s0, int tid)
{
    unsigned kdst = sb + (AT_K + buf*8448)*2;
    unsigned vdst = sb + (AT_V + buf*8448)*2;
    #pragma unroll
    for (int i = 0; i < 2; i++){
        int id = tid + i*512;
        int r = id >> 5, c8 = (id & 31) << 3;
        long grow = (long)(b*LQ + s0 + r)*256 + c8;
        cpa16(kdst + (r*QH + c8)*2, Km + grow);
        cpa16(vdst + (r*QH + c8)*2, Vm + grow);
    }
    {
        int r = tid >> 3, c4 = (tid & 7) << 2;
        unsigned cdst = sb + AT_CB + buf*(64*CS_STR*4) + (r*CS_STR + c4)*4;
        cpa16(cdst, comp + (long)(b*LQ + l0 + r)*LQ + s0 + c4);
    }
    if (tid < 32)
        cpa4(sb + AT_SMS + buf*128 + tid*4, smask + b*LQ + s0 + tid);
}

__global__ void __launch_bounds__(512, 1) k_attn(
    const __half* __restrict__ Qm, const __half* __restrict__ Km, const __half* __restrict__ Vm,
    const float* __restrict__ comp, const int* __restrict__ xmask, const int* __restrict__ smask)
{
    extern __shared__ unsigned char smraw[];
    __half* smh = (__half*)smraw;
    __half* Qh = smh;
    float*  CsBase = (float*)(smraw + AT_CB);
    int*    smsBase = (int*)(smraw + AT_SMS);
    int*    xm = (int*)(smraw + AT_XM);

    int tid = threadIdx.x;
    int w = tid >> 5, lane = tid & 31;
    int h = w & 3, wm = w >> 2;
    int g4 = lane >> 2, tig = lane & 3;
    int lrow = (lane & 7) + ((lane >> 3) & 1)*8;
    int lcol8 = (lane >> 4)*8;
    int l0 = blockIdx.x * 64;
    int sp = blockIdx.y, b = blockIdx.z;
    int dbase = h*64;

    unsigned sb = (unsigned)__cvta_generic_to_shared(smh);
    unsigned qb = sb;

    int sbase = sp*(LQ/SPLITS);
    attn_issue_tile(Km, Vm, comp, smask, sb, 0, b, l0, sbase, tid);
    CPA_COMMIT();

    #pragma unroll
    for (int i = 0; i < 4; i++){
        int id = tid + i*512;
        int r = id >> 5, c8 = (id & 31) << 3;
        *(uint4*)&Qh[r*QH + c8] = *(const uint4*)(Qm + (b*LQ + l0 + r)*256 + c8);
    }
    if (tid < 64) xm[tid] = xmask[b*LQ + l0 + tid];

    float o[8][4];
    #pragma unroll
    for (int nt = 0; nt < 8; nt++)
        #pragma unroll
        for (int i = 0; i < 4; i++) o[nt][i] = 0.f;
    float rmax[2] = {-1e30f, -1e30f};
    float rsum[2] = {0.f, 0.f};

    CPA_WAIT0();
    __syncthreads();

    unsigned qa[4][4];
    #pragma unroll
    for (int kk = 0; kk < 4; kk++)
        ldsm4(qa[kk], qb + ((wm*16 + lrow)*QH + dbase + kk*16 + lcol8)*2);

    int rl = wm*16 + g4;
    const int NT = (LQ/SPLITS)/32;
    for (int t = 0; t < NT; t++){
        int buf = t & 1;
        unsigned kb = sb + (AT_K + buf*8448)*2;
        unsigned vb = sb + (AT_V + buf*8448)*2;
        float* Cs = CsBase + buf*(64*CS_STR);
        int*   sms = smsBase + buf*32;

        if (t + 1 < NT){
            attn_issue_tile(Km, Vm, comp, smask, sb, buf^1, b, l0, sbase + (t+1)*32, tid);
            CPA_COMMIT();
        }

        float S[4][4];
        #pragma unroll
        for (int nt = 0; nt < 4; nt++)
            #pragma unroll
            for (int i = 0; i < 4; i++) S[nt][i] = 0.f;
        #pragma unroll
        for (int kk = 0; kk < 4; kk++){
            int k0 = dbase + kk*16;
            #pragma unroll
            for (int sh = 0; sh < 2; sh++){
                unsigned bk[4];
                ldsm4(bk, kb + ((sh*16 + lrow)*QH + k0 + lcol8)*2);
                unsigned b0[2] = {bk[0], bk[2]};
                unsigned b1[2] = {bk[1], bk[3]};
                mma16(S[sh*2],   qa[kk], b0);
                mma16(S[sh*2+1], qa[kk], b1);
            }
        }

        int xml = xm[rl], xmh = xm[rl + 8];
        float tmaxl = -1e30f, tmaxh = -1e30f;
        #pragma unroll
        for (int nt = 0; nt < 4; nt++){
            int se = nt*8 + 2*tig;
            int2 m2 = *(const int2*)&sms[se];
            float2 cl = *(const float2*)&Cs[rl*CS_STR + se];
            float2 ch = *(const float2*)&Cs[(rl+8)*CS_STR + se];
            float v0 = (xml && !m2.x) ? -1e30f : S[nt][0]*cl.x;
            float v1 = (xml && !m2.y) ? -1e30f : S[nt][1]*cl.y;
            float v2 = (xmh && !m2.x) ? -1e30f : S[nt][2]*ch.x;
            float v3 = (xmh && !m2.y) ? -1e30f : S[nt][3]*ch.y;
            S[nt][0]=v0; S[nt][1]=v1; S[nt][2]=v2; S[nt][3]=v3;
            tmaxl = fmaxf(tmaxl, fmaxf(v0, v1));
            tmaxh = fmaxf(tmaxh, fmaxf(v2, v3));
        }
        tmaxl = fmaxf(tmaxl, __shfl_xor_sync(~0u, tmaxl, 1));
        tmaxl = fmaxf(tmaxl, __shfl_xor_sync(~0u, tmaxl, 2));
        tmaxh = fmaxf(tmaxh, __shfl_xor_sync(~0u, tmaxh, 1));
        tmaxh = fmaxf(tmaxh, __shfl_xor_sync(~0u, tmaxh, 2));
        float ml = fmaxf(rmax[0], tmaxl), mh = fmaxf(rmax[1], tmaxh);
        float al = fast_exp(rmax[0] - ml), ah = fast_exp(rmax[1] - mh);
        rmax[0] = ml; rmax[1] = mh;
        float tsl = 0.f, tsh = 0.f;
        unsigned Pa[4][2];
        #pragma unroll
        for (int nt = 0; nt < 4; nt++){
            float p0 = fast_exp(S[nt][0] - ml);
            float p1 = fast_exp(S[nt][1] - ml);
            float p2 = fast_exp(S[nt][2] - mh);
            float p3 = fast_exp(S[nt][3] - mh);
            tsl += p0 + p1; tsh += p2 + p3;
            Pa[nt][0] = h2pk(p0, p1);
            Pa[nt][1] = h2pk(p2, p3);
        }
        tsl += __shfl_xor_sync(~0u, tsl, 1); tsl += __shfl_xor_sync(~0u, tsl, 2);
        tsh += __shfl_xor_sync(~0u, tsh, 1); tsh += __shfl_xor_sync(~0u, tsh, 2);
        rsum[0] = rsum[0]*al + tsl;
        rsum[1] = rsum[1]*ah + tsh;
        #pragma unroll
        for (int nt = 0; nt < 8; nt++){
            o[nt][0] *= al; o[nt][1] *= al;
            o[nt][2] *= ah; o[nt][3] *= ah;
        }

        #pragma unroll
        for (int kk = 0; kk < 2; kk++){
            unsigned a[4] = {Pa[kk*2][0], Pa[kk*2][1], Pa[kk*2+1][0], Pa[kk*2+1][1]};
            #pragma unroll
            for (int j = 0; j < 4; j++){
                unsigned bv[4];
                ldsm4t(bv, vb + ((kk*16 + lrow)*QH + dbase + j*16 + lcol8)*2);
                unsigned b0[2] = {bv[0], bv[1]};
                unsigned b1[2] = {bv[2], bv[3]};
                mma16(o[2*j],   a, b0);
                mma16(o[2*j+1], a, b1);
            }
        }

        if (t + 1 < NT){
            CPA_WAIT0();
            __syncthreads();
        }
    }

    long prow = (long)(sp*MROWS + b*LQ + l0 + rl);
    #pragma unroll
    for (int nt = 0; nt < 8; nt++){
        int col = dbase + nt*8 + 2*tig;
        *(unsigned*)(g_parth + prow*256 + col)     = h2pk(o[nt][0], o[nt][1]);
        *(unsigned*)(g_parth + (prow+8)*256 + col) = h2pk(o[nt][2], o[nt][3]);
    }
    if (tig == 0){
        long base = (prow*4 + h)*2;
        g_pstat[base]   = rmax[0];
        g_pstat[base+1] = rsum[0];
        long baseh = ((prow+8)*4 + h)*2;
        g_pstat[baseh]   = rmax[1];
        g_pstat[baseh+1] = rsum[1];
    }
}

// ---------------------------------------------------------------------------
extern "C" void kernel_launch(void* const* d_in, const int* in_sizes, int n_in,
                              void* d_out, int out_size)
{
    const float* x    = (const float*)d_in[0];
    const float* src  = (const float*)d_in[1];
    const float* xpe  = (const float*)d_in[2];
    const float* spe  = (const float*)d_in[3];
    const int* xmask  = (const int*)d_in[4];
    const int* smask  = (const int*)d_in[5];
    const float* comp = (const float*)d_in[6];
    const float* Wq   = (const float*)d_in[7];
    const float* Wk   = (const float*)d_in[8];
    const float* Wv   = (const float*)d_in[9];
    const float* Wmg  = (const float*)d_in[10];
    const float* Wm1  = (const float*)d_in[11];
    const float* Wm2  = (const float*)d_in[12];
    const float* ln1g = (const float*)d_in[13];
    const float* ln1b = (const float*)d_in[14];
    const float* ln2g = (const float*)d_in[15];
    const float* ln2b = (const float*)d_in[16];
    float* out = (float*)d_out;

    __half *Qp, *Kp, *Vp;
    cudaGetSymbolAddress((void**)&Qp, g_Qh);
    cudaGetSymbolAddress((void**)&Kp, g_Kh);
    cudaGetSymbolAddress((void**)&Vp, g_Vh);

    cudaFuncSetAttribute(k_attn, cudaFuncAttributeMaxDynamicSharedMemorySize, ATTN_BYTES);

    k_prep<<<(int)PREP_GRID, 256>>>(Wq, Wk, Wv, Wmg, Wm1, Wm2);
    k_qkv <<<dim3(MROWS/32, 1, 3), 256, SM_GEMM>>>(x, xpe, src, spe);
    k_attn<<<dim3(LQ/64, SPLITS, BSZ), 512, ATTN_BYTES>>>(Qp, Kp, Vp, comp, xmask, smask);
    k_merge<<<MROWS/16, 256, SM_MERGE>>>(ln1g, ln1b);
    k_mlp1<<<dim3(MROWS/32, 2), 256, SM_GEMM>>>(x);
    k_mlp2<<<MROWS/32, 256, SM_GEMM>>>(ln2g, ln2b, x, out);
}